// round 1
// baseline (speedup 1.0000x reference)
#include <cuda_runtime.h>
#include <math.h>

#define BB   4
#define SS   2048
#define DD   512
#define HH   8
#define HDIM 64
#define MTOT (BB*SS)   // 8192

// Scratch (static device globals — allocation-free per harness rules)
__device__ float g_q   [BB*HH*SS*HDIM];
__device__ float g_k   [BB*HH*SS*HDIM];
__device__ float g_v   [BB*HH*SS*HDIM];
__device__ float g_attn[BB*HH*SS*HDIM];

// ---------------------------------------------------------------------------
// Projection GEMM: C = A @ Wq + bq  for A in {query,key,value} (blockIdx.z),
// scattered directly into [B,H,S,HD] layout.
// Tile: 64(M) x 64(N), BK=32, 256 threads, 4x4 per thread.
// ---------------------------------------------------------------------------
__global__ __launch_bounds__(256)
void proj_kernel(const float* __restrict__ q,
                 const float* __restrict__ k,
                 const float* __restrict__ v,
                 const float* __restrict__ W,
                 const float* __restrict__ bias)
{
    __shared__ float As[64*32];   // [row m][k]   (reads: broadcast)
    __shared__ float Ws[32*64];   // [k][col n]   (reads: row-spread, conflict-free)

    const int z = blockIdx.z;
    const float* A = (z == 0) ? q : ((z == 1) ? k : v);
    float* out = (z == 0) ? g_q : ((z == 1) ? g_k : g_v);

    const int m0 = blockIdx.x * 64;
    const int n0 = blockIdx.y * 64;
    const int tid = threadIdx.x;
    const int ty = tid >> 4, tx = tid & 15;

    float acc[4][4] = {};

    for (int k0 = 0; k0 < DD; k0 += 32) {
        #pragma unroll
        for (int rep = 0; rep < 2; rep++) {
            int f4 = tid + rep*256;
            int row = f4 >> 3, c4 = f4 & 7;
            *(float4*)&As[row*32 + c4*4] =
                *(const float4*)&A[(m0+row)*DD + k0 + c4*4];
        }
        #pragma unroll
        for (int rep = 0; rep < 2; rep++) {
            int f4 = tid + rep*256;
            int row = f4 >> 4, c4 = f4 & 15;
            *(float4*)&Ws[row*64 + c4*4] =
                *(const float4*)&W[(k0+row)*DD + n0 + c4*4];
        }
        __syncthreads();

        #pragma unroll
        for (int k4 = 0; k4 < 8; k4++) {
            float a_[4][4];
            #pragma unroll
            for (int r = 0; r < 4; r++) {
                float4 t = *(const float4*)&As[(4*ty+r)*32 + k4*4];
                a_[r][0]=t.x; a_[r][1]=t.y; a_[r][2]=t.z; a_[r][3]=t.w;
            }
            #pragma unroll
            for (int kk = 0; kk < 4; kk++) {
                float4 wv = *(const float4*)&Ws[(k4*4+kk)*64 + 4*tx];
                float wc[4] = {wv.x, wv.y, wv.z, wv.w};
                #pragma unroll
                for (int r = 0; r < 4; r++)
                    #pragma unroll
                    for (int c = 0; c < 4; c++)
                        acc[r][c] = fmaf(a_[r][kk], wc[c], acc[r][c]);
            }
        }
        __syncthreads();
    }

    // Epilogue: n0 tile maps to head h = blockIdx.y (64-wide heads)
    const int b  = m0 >> 11;       // m0 / 2048
    const int s0 = m0 & 2047;
    const int h  = blockIdx.y;
    float4 bv = *(const float4*)&bias[n0 + 4*tx];
    #pragma unroll
    for (int r = 0; r < 4; r++) {
        int srow = s0 + 4*ty + r;
        float4 o;
        o.x = acc[r][0] + bv.x;
        o.y = acc[r][1] + bv.y;
        o.z = acc[r][2] + bv.z;
        o.w = acc[r][3] + bv.w;
        *(float4*)&out[((b*HH + h)*SS + srow)*HDIM + 4*tx] = o;
    }
}

// ---------------------------------------------------------------------------
// Flash attention: per (b,h, 64-row Q tile), online softmax over 32 K tiles.
// smem: Qs[i][d], KPs = K^T[d][j] (then reused for P[i][j]), Vs[j][d].
// All reads are broadcast or row-spread (conflict-free); the K-transpose
// store is column-lane-assigned so it is also conflict-free.
// ---------------------------------------------------------------------------
__global__ __launch_bounds__(256)
void attn_kernel()
{
    __shared__ float Qs [64*64];
    __shared__ float KPs[64*64];   // K^T, then P (aliased)
    __shared__ float Vs [64*64];

    const int qt  = blockIdx.x;    // 0..31
    const int bh  = blockIdx.y;    // 0..31  (b*8 + h)
    const int tid = threadIdx.x;
    const int ty = tid >> 4, tx = tid & 15;

    const float* Qg = g_q + (bh*SS + qt*64)*HDIM;
    const float* Kg = g_k + bh*SS*HDIM;
    const float* Vg = g_v + bh*SS*HDIM;

    // Load Q tile (natural, coalesced)
    #pragma unroll
    for (int rep = 0; rep < 4; rep++) {
        int f4 = tid + rep*256;
        int row = f4 >> 4, c4 = f4 & 15;
        *(float4*)&Qs[row*64 + c4*4] = *(const float4*)&Qg[row*64 + c4*4];
    }

    float acc[4][4] = {};
    float mrow[4], lrow[4];
    #pragma unroll
    for (int r = 0; r < 4; r++) { mrow[r] = -INFINITY; lrow[r] = 0.f; }

    for (int kt = 0; kt < 32; kt++) {
        __syncthreads();   // protect KPs/Vs from previous iteration's readers

        // K tile -> KPs transposed [d][j]; lanes assigned column-major so
        // the scalar transpose stores are bank-conflict-free.
        const float* Kt = Kg + kt*64*HDIM;
        #pragma unroll
        for (int rep = 0; rep < 4; rep++) {
            int f4 = tid + rep*256;
            int j  = f4 & 63;
            int c4 = f4 >> 6;          // 0..15
            float4 t = *(const float4*)&Kt[j*64 + c4*4];
            KPs[(c4*4+0)*64 + j] = t.x;
            KPs[(c4*4+1)*64 + j] = t.y;
            KPs[(c4*4+2)*64 + j] = t.z;
            KPs[(c4*4+3)*64 + j] = t.w;
        }
        // V tile (natural, coalesced)
        const float* Vt = Vg + kt*64*HDIM;
        #pragma unroll
        for (int rep = 0; rep < 4; rep++) {
            int f4 = tid + rep*256;
            int row = f4 >> 4, c4 = f4 & 15;
            *(float4*)&Vs[row*64 + c4*4] = *(const float4*)&Vt[row*64 + c4*4];
        }
        __syncthreads();

        // S = Q @ K^T  (raw, scale applied inside softmax)
        float sc[4][4] = {};
        #pragma unroll
        for (int d4 = 0; d4 < 16; d4++) {
            float qf[4][4];
            #pragma unroll
            for (int r = 0; r < 4; r++) {
                float4 t = *(const float4*)&Qs[(4*ty+r)*64 + d4*4];
                qf[r][0]=t.x; qf[r][1]=t.y; qf[r][2]=t.z; qf[r][3]=t.w;
            }
            #pragma unroll
            for (int dd = 0; dd < 4; dd++) {
                float4 kf = *(const float4*)&KPs[(d4*4+dd)*64 + 4*tx];
                float kc[4] = {kf.x, kf.y, kf.z, kf.w};
                #pragma unroll
                for (int r = 0; r < 4; r++)
                    #pragma unroll
                    for (int c = 0; c < 4; c++)
                        sc[r][c] = fmaf(qf[r][dd], kc[c], sc[r][c]);
            }
        }

        // Online softmax (scale = 1/sqrt(64) = 0.125)
        #pragma unroll
        for (int r = 0; r < 4; r++) {
            float rm = fmaxf(fmaxf(sc[r][0], sc[r][1]), fmaxf(sc[r][2], sc[r][3]));
            #pragma unroll
            for (int o = 1; o < 16; o <<= 1)
                rm = fmaxf(rm, __shfl_xor_sync(0xffffffffu, rm, o));
            float newm = fmaxf(mrow[r], rm * 0.125f);
            float corr = __expf(mrow[r] - newm);
            mrow[r] = newm;

            float rs = 0.f;
            #pragma unroll
            for (int c = 0; c < 4; c++) {
                float p = __expf(fmaf(sc[r][c], 0.125f, -newm));
                sc[r][c] = p;
                rs += p;
            }
            #pragma unroll
            for (int o = 1; o < 16; o <<= 1)
                rs += __shfl_xor_sync(0xffffffffu, rs, o);
            lrow[r] = lrow[r] * corr + rs;
            #pragma unroll
            for (int c = 0; c < 4; c++) acc[r][c] *= corr;
        }

        __syncthreads();   // all threads done reading K^T
        // Store P over KPs (natural [i][j], coalesced float4)
        #pragma unroll
        for (int r = 0; r < 4; r++)
            *(float4*)&KPs[(4*ty+r)*64 + 4*tx] =
                make_float4(sc[r][0], sc[r][1], sc[r][2], sc[r][3]);
        __syncthreads();

        // O += P @ V
        #pragma unroll
        for (int j4 = 0; j4 < 16; j4++) {
            float pf[4][4];
            #pragma unroll
            for (int r = 0; r < 4; r++) {
                float4 t = *(const float4*)&KPs[(4*ty+r)*64 + j4*4];
                pf[r][0]=t.x; pf[r][1]=t.y; pf[r][2]=t.z; pf[r][3]=t.w;
            }
            #pragma unroll
            for (int jj = 0; jj < 4; jj++) {
                float4 vv = *(const float4*)&Vs[(j4*4+jj)*64 + 4*tx];
                float vc[4] = {vv.x, vv.y, vv.z, vv.w};
                #pragma unroll
                for (int r = 0; r < 4; r++)
                    #pragma unroll
                    for (int c = 0; c < 4; c++)
                        acc[r][c] = fmaf(pf[r][jj], vc[c], acc[r][c]);
            }
        }
    }

    // Epilogue: normalize and write [B,H,S,HD]
    float* Og = g_attn + (bh*SS + qt*64)*HDIM;
    #pragma unroll
    for (int r = 0; r < 4; r++) {
        float inv = 1.f / lrow[r];
        float4 o = make_float4(acc[r][0]*inv, acc[r][1]*inv,
                               acc[r][2]*inv, acc[r][3]*inv);
        *(float4*)&Og[(4*ty+r)*64 + 4*tx] = o;
    }
}

// ---------------------------------------------------------------------------
// Output projection: out[m,n] = sum_k attn[m,k] * Wo[k,n] + bo[n]
// attn gathered from [B,H,S,HD] layout.
// ---------------------------------------------------------------------------
__global__ __launch_bounds__(256)
void outproj_kernel(const float* __restrict__ W,
                    const float* __restrict__ bias,
                    float* __restrict__ out)
{
    __shared__ float As[64*32];
    __shared__ float Ws[32*64];

    const int m0 = blockIdx.x * 64;
    const int n0 = blockIdx.y * 64;
    const int b  = m0 >> 11;
    const int s0 = m0 & 2047;
    const int tid = threadIdx.x;
    const int ty = tid >> 4, tx = tid & 15;

    float acc[4][4] = {};

    for (int k0 = 0; k0 < DD; k0 += 32) {
        const int h   = k0 >> 6;
        const int hd0 = k0 & 63;
        #pragma unroll
        for (int rep = 0; rep < 2; rep++) {
            int f4 = tid + rep*256;
            int row = f4 >> 3, c4 = f4 & 7;
            *(float4*)&As[row*32 + c4*4] =
                *(const float4*)&g_attn[((b*HH + h)*SS + s0 + row)*HDIM + hd0 + c4*4];
        }
        #pragma unroll
        for (int rep = 0; rep < 2; rep++) {
            int f4 = tid + rep*256;
            int row = f4 >> 4, c4 = f4 & 15;
            *(float4*)&Ws[row*64 + c4*4] =
                *(const float4*)&W[(k0+row)*DD + n0 + c4*4];
        }
        __syncthreads();

        #pragma unroll
        for (int k4 = 0; k4 < 8; k4++) {
            float a_[4][4];
            #pragma unroll
            for (int r = 0; r < 4; r++) {
                float4 t = *(const float4*)&As[(4*ty+r)*32 + k4*4];
                a_[r][0]=t.x; a_[r][1]=t.y; a_[r][2]=t.z; a_[r][3]=t.w;
            }
            #pragma unroll
            for (int kk = 0; kk < 4; kk++) {
                float4 wv = *(const float4*)&Ws[(k4*4+kk)*64 + 4*tx];
                float wc[4] = {wv.x, wv.y, wv.z, wv.w};
                #pragma unroll
                for (int r = 0; r < 4; r++)
                    #pragma unroll
                    for (int c = 0; c < 4; c++)
                        acc[r][c] = fmaf(a_[r][kk], wc[c], acc[r][c]);
            }
        }
        __syncthreads();
    }

    float4 bv = *(const float4*)&bias[n0 + 4*tx];
    #pragma unroll
    for (int r = 0; r < 4; r++) {
        int m = m0 + 4*ty + r;
        float4 o;
        o.x = acc[r][0] + bv.x;
        o.y = acc[r][1] + bv.y;
        o.z = acc[r][2] + bv.z;
        o.w = acc[r][3] + bv.w;
        *(float4*)&out[m*DD + n0 + 4*tx] = o;
    }
}

// ---------------------------------------------------------------------------
extern "C" void kernel_launch(void* const* d_in, const int* in_sizes, int n_in,
                              void* d_out, int out_size)
{
    const float* query = (const float*)d_in[0];
    const float* key   = (const float*)d_in[1];
    const float* value = (const float*)d_in[2];
    const float* Wq    = (const float*)d_in[3];
    const float* bq    = (const float*)d_in[4];
    const float* Wo    = (const float*)d_in[5];
    const float* bo    = (const float*)d_in[6];
    float* out = (float*)d_out;

    proj_kernel  <<<dim3(MTOT/64, DD/64, 3), 256>>>(query, key, value, Wq, bq);
    attn_kernel  <<<dim3(SS/64, BB*HH),      256>>>();
    outproj_kernel<<<dim3(MTOT/64, DD/64),   256>>>(Wo, bo, out);
}

// round 2
// speedup vs baseline: 1.0194x; 1.0194x over previous
#include <cuda_runtime.h>
#include <math.h>

#define BB   4
#define SS   2048
#define DD   512
#define HH   8
#define HDIM 64
#define MTOT (BB*SS)   // 8192

typedef unsigned long long u64;

// ---- packed f32x2 helpers (Blackwell PTX) ----------------------------------
__device__ __forceinline__ u64 bcast2(float x) {
    u64 d; asm("mov.b64 %0, {%1, %1};" : "=l"(d) : "f"(x)); return d;
}
__device__ __forceinline__ void unpack2(u64 v, float& lo, float& hi) {
    asm("mov.b64 {%0, %1}, %2;" : "=f"(lo), "=f"(hi) : "l"(v));
}
__device__ __forceinline__ void ffma2(u64& d, u64 a, u64 b) {
    asm("fma.rn.f32x2 %0, %1, %2, %0;" : "+l"(d) : "l"(a), "l"(b));
}
__device__ __forceinline__ void fmul2(u64& d, u64 a) {
    asm("mul.rn.f32x2 %0, %0, %1;" : "+l"(d) : "l"(a));
}

// Scratch (static device globals — allocation-free per harness rules)
__device__ float g_q   [BB*HH*SS*HDIM];
__device__ float g_k   [BB*HH*SS*HDIM];
__device__ float g_v   [BB*HH*SS*HDIM];
__device__ float g_attn[BB*HH*SS*HDIM];

// ---------------------------------------------------------------------------
// Projection GEMM: C = A @ Wq + bq  for A in {query,key,value} (blockIdx.z),
// scattered directly into [B,H,S,HD] layout. 64x64 tile, BK=32, 256 thr, 4x4.
// Inner product uses packed fma.rn.f32x2 (2 FLOP / fma slot).
// ---------------------------------------------------------------------------
__global__ __launch_bounds__(256)
void proj_kernel(const float* __restrict__ q,
                 const float* __restrict__ k,
                 const float* __restrict__ v,
                 const float* __restrict__ W,
                 const float* __restrict__ bias)
{
    __shared__ float As[64*32];   // [m][k]
    __shared__ float Ws[32*64];   // [k][n]

    const int z = blockIdx.z;
    const float* A = (z == 0) ? q : ((z == 1) ? k : v);
    float* out = (z == 0) ? g_q : ((z == 1) ? g_k : g_v);

    const int m0 = blockIdx.x * 64;
    const int n0 = blockIdx.y * 64;
    const int tid = threadIdx.x;
    const int ty = tid >> 4, tx = tid & 15;

    u64 acc2[4][2] = {};   // 4 rows x 2 col-pairs (f32x2)

    for (int k0 = 0; k0 < DD; k0 += 32) {
        #pragma unroll
        for (int rep = 0; rep < 2; rep++) {
            int f4 = tid + rep*256;
            int row = f4 >> 3, c4 = f4 & 7;
            *(float4*)&As[row*32 + c4*4] =
                *(const float4*)&A[(m0+row)*DD + k0 + c4*4];
        }
        #pragma unroll
        for (int rep = 0; rep < 2; rep++) {
            int f4 = tid + rep*256;
            int row = f4 >> 4, c4 = f4 & 15;
            *(float4*)&Ws[row*64 + c4*4] =
                *(const float4*)&W[(k0+row)*DD + n0 + c4*4];
        }
        __syncthreads();

        #pragma unroll
        for (int k4 = 0; k4 < 8; k4++) {
            float a_[4][4];
            #pragma unroll
            for (int r = 0; r < 4; r++) {
                float4 t = *(const float4*)&As[(4*ty+r)*32 + k4*4];
                a_[r][0]=t.x; a_[r][1]=t.y; a_[r][2]=t.z; a_[r][3]=t.w;
            }
            #pragma unroll
            for (int kk = 0; kk < 4; kk++) {
                ulonglong2 wv = *(const ulonglong2*)&Ws[(k4*4+kk)*64 + 4*tx];
                #pragma unroll
                for (int r = 0; r < 4; r++) {
                    u64 ab = bcast2(a_[r][kk]);
                    ffma2(acc2[r][0], ab, wv.x);
                    ffma2(acc2[r][1], ab, wv.y);
                }
            }
        }
        __syncthreads();
    }

    const int b  = m0 >> 11;
    const int s0 = m0 & 2047;
    const int h  = blockIdx.y;
    float4 bv = *(const float4*)&bias[n0 + 4*tx];
    #pragma unroll
    for (int r = 0; r < 4; r++) {
        int srow = s0 + 4*ty + r;
        float4 o;
        unpack2(acc2[r][0], o.x, o.y);
        unpack2(acc2[r][1], o.z, o.w);
        o.x += bv.x; o.y += bv.y; o.z += bv.z; o.w += bv.w;
        *(float4*)&out[((b*HH + h)*SS + srow)*HDIM + 4*tx] = o;
    }
}

// ---------------------------------------------------------------------------
// Flash attention with f32x2 inner products.
// ---------------------------------------------------------------------------
__global__ __launch_bounds__(256)
void attn_kernel()
{
    __shared__ float Qs [64*64];
    __shared__ float KPs[64*64];   // K^T, then P (aliased)
    __shared__ float Vs [64*64];

    const int qt  = blockIdx.x;
    const int bh  = blockIdx.y;
    const int tid = threadIdx.x;
    const int ty = tid >> 4, tx = tid & 15;

    const float* Qg = g_q + (bh*SS + qt*64)*HDIM;
    const float* Kg = g_k + bh*SS*HDIM;
    const float* Vg = g_v + bh*SS*HDIM;

    #pragma unroll
    for (int rep = 0; rep < 4; rep++) {
        int f4 = tid + rep*256;
        int row = f4 >> 4, c4 = f4 & 15;
        *(float4*)&Qs[row*64 + c4*4] = *(const float4*)&Qg[row*64 + c4*4];
    }

    u64 acc2[4][2] = {};
    float mrow[4], lrow[4];
    #pragma unroll
    for (int r = 0; r < 4; r++) { mrow[r] = -INFINITY; lrow[r] = 0.f; }

    for (int kt = 0; kt < 32; kt++) {
        __syncthreads();

        // K tile -> KPs transposed [d][j] (column-lane-assigned: conflict-free)
        const float* Kt = Kg + kt*64*HDIM;
        #pragma unroll
        for (int rep = 0; rep < 4; rep++) {
            int f4 = tid + rep*256;
            int j  = f4 & 63;
            int c4 = f4 >> 6;
            float4 t = *(const float4*)&Kt[j*64 + c4*4];
            KPs[(c4*4+0)*64 + j] = t.x;
            KPs[(c4*4+1)*64 + j] = t.y;
            KPs[(c4*4+2)*64 + j] = t.z;
            KPs[(c4*4+3)*64 + j] = t.w;
        }
        const float* Vt = Vg + kt*64*HDIM;
        #pragma unroll
        for (int rep = 0; rep < 4; rep++) {
            int f4 = tid + rep*256;
            int row = f4 >> 4, c4 = f4 & 15;
            *(float4*)&Vs[row*64 + c4*4] = *(const float4*)&Vt[row*64 + c4*4];
        }
        __syncthreads();

        // S = Q @ K^T (packed pairs along j)
        u64 sc2[4][2] = {};
        #pragma unroll
        for (int d4 = 0; d4 < 16; d4++) {
            float qf[4][4];
            #pragma unroll
            for (int r = 0; r < 4; r++) {
                float4 t = *(const float4*)&Qs[(4*ty+r)*64 + d4*4];
                qf[r][0]=t.x; qf[r][1]=t.y; qf[r][2]=t.z; qf[r][3]=t.w;
            }
            #pragma unroll
            for (int dd = 0; dd < 4; dd++) {
                ulonglong2 kf = *(const ulonglong2*)&KPs[(d4*4+dd)*64 + 4*tx];
                #pragma unroll
                for (int r = 0; r < 4; r++) {
                    u64 qb = bcast2(qf[r][dd]);
                    ffma2(sc2[r][0], qb, kf.x);
                    ffma2(sc2[r][1], qb, kf.y);
                }
            }
        }

        // Online softmax (scale = 0.125)
        float sc[4][4];
        #pragma unroll
        for (int r = 0; r < 4; r++) {
            unpack2(sc2[r][0], sc[r][0], sc[r][1]);
            unpack2(sc2[r][1], sc[r][2], sc[r][3]);
        }
        #pragma unroll
        for (int r = 0; r < 4; r++) {
            float rm = fmaxf(fmaxf(sc[r][0], sc[r][1]), fmaxf(sc[r][2], sc[r][3]));
            #pragma unroll
            for (int o = 1; o < 16; o <<= 1)
                rm = fmaxf(rm, __shfl_xor_sync(0xffffffffu, rm, o));
            float newm = fmaxf(mrow[r], rm * 0.125f);
            float corr = __expf(mrow[r] - newm);
            mrow[r] = newm;

            float rs = 0.f;
            #pragma unroll
            for (int c = 0; c < 4; c++) {
                float p = __expf(fmaf(sc[r][c], 0.125f, -newm));
                sc[r][c] = p;
                rs += p;
            }
            #pragma unroll
            for (int o = 1; o < 16; o <<= 1)
                rs += __shfl_xor_sync(0xffffffffu, rs, o);
            lrow[r] = lrow[r] * corr + rs;
            u64 cb = bcast2(corr);
            fmul2(acc2[r][0], cb);
            fmul2(acc2[r][1], cb);
        }

        __syncthreads();
        #pragma unroll
        for (int r = 0; r < 4; r++)
            *(float4*)&KPs[(4*ty+r)*64 + 4*tx] =
                make_float4(sc[r][0], sc[r][1], sc[r][2], sc[r][3]);
        __syncthreads();

        // O += P @ V (packed pairs along d)
        #pragma unroll
        for (int j4 = 0; j4 < 16; j4++) {
            float pf[4][4];
            #pragma unroll
            for (int r = 0; r < 4; r++) {
                float4 t = *(const float4*)&KPs[(4*ty+r)*64 + j4*4];
                pf[r][0]=t.x; pf[r][1]=t.y; pf[r][2]=t.z; pf[r][3]=t.w;
            }
            #pragma unroll
            for (int jj = 0; jj < 4; jj++) {
                ulonglong2 vv = *(const ulonglong2*)&Vs[(j4*4+jj)*64 + 4*tx];
                #pragma unroll
                for (int r = 0; r < 4; r++) {
                    u64 pb = bcast2(pf[r][jj]);
                    ffma2(acc2[r][0], pb, vv.x);
                    ffma2(acc2[r][1], pb, vv.y);
                }
            }
        }
    }

    float* Og = g_attn + (bh*SS + qt*64)*HDIM;
    #pragma unroll
    for (int r = 0; r < 4; r++) {
        float inv = 1.f / lrow[r];
        float4 o;
        unpack2(acc2[r][0], o.x, o.y);
        unpack2(acc2[r][1], o.z, o.w);
        o.x *= inv; o.y *= inv; o.z *= inv; o.w *= inv;
        *(float4*)&Og[(4*ty+r)*64 + 4*tx] = o;
    }
}

// ---------------------------------------------------------------------------
// Output projection with f32x2 inner products.
// ---------------------------------------------------------------------------
__global__ __launch_bounds__(256)
void outproj_kernel(const float* __restrict__ W,
                    const float* __restrict__ bias,
                    float* __restrict__ out)
{
    __shared__ float As[64*32];
    __shared__ float Ws[32*64];

    const int m0 = blockIdx.x * 64;
    const int n0 = blockIdx.y * 64;
    const int b  = m0 >> 11;
    const int s0 = m0 & 2047;
    const int tid = threadIdx.x;
    const int ty = tid >> 4, tx = tid & 15;

    u64 acc2[4][2] = {};

    for (int k0 = 0; k0 < DD; k0 += 32) {
        const int h   = k0 >> 6;
        const int hd0 = k0 & 63;
        #pragma unroll
        for (int rep = 0; rep < 2; rep++) {
            int f4 = tid + rep*256;
            int row = f4 >> 3, c4 = f4 & 7;
            *(float4*)&As[row*32 + c4*4] =
                *(const float4*)&g_attn[((b*HH + h)*SS + s0 + row)*HDIM + hd0 + c4*4];
        }
        #pragma unroll
        for (int rep = 0; rep < 2; rep++) {
            int f4 = tid + rep*256;
            int row = f4 >> 4, c4 = f4 & 15;
            *(float4*)&Ws[row*64 + c4*4] =
                *(const float4*)&W[(k0+row)*DD + n0 + c4*4];
        }
        __syncthreads();

        #pragma unroll
        for (int k4 = 0; k4 < 8; k4++) {
            float a_[4][4];
            #pragma unroll
            for (int r = 0; r < 4; r++) {
                float4 t = *(const float4*)&As[(4*ty+r)*32 + k4*4];
                a_[r][0]=t.x; a_[r][1]=t.y; a_[r][2]=t.z; a_[r][3]=t.w;
            }
            #pragma unroll
            for (int kk = 0; kk < 4; kk++) {
                ulonglong2 wv = *(const ulonglong2*)&Ws[(k4*4+kk)*64 + 4*tx];
                #pragma unroll
                for (int r = 0; r < 4; r++) {
                    u64 ab = bcast2(a_[r][kk]);
                    ffma2(acc2[r][0], ab, wv.x);
                    ffma2(acc2[r][1], ab, wv.y);
                }
            }
        }
        __syncthreads();
    }

    float4 bv = *(const float4*)&bias[n0 + 4*tx];
    #pragma unroll
    for (int r = 0; r < 4; r++) {
        int m = m0 + 4*ty + r;
        float4 o;
        unpack2(acc2[r][0], o.x, o.y);
        unpack2(acc2[r][1], o.z, o.w);
        o.x += bv.x; o.y += bv.y; o.z += bv.z; o.w += bv.w;
        *(float4*)&out[m*DD + n0 + 4*tx] = o;
    }
}

// ---------------------------------------------------------------------------
extern "C" void kernel_launch(void* const* d_in, const int* in_sizes, int n_in,
                              void* d_out, int out_size)
{
    const float* query = (const float*)d_in[0];
    const float* key   = (const float*)d_in[1];
    const float* value = (const float*)d_in[2];
    const float* Wq    = (const float*)d_in[3];
    const float* bq    = (const float*)d_in[4];
    const float* Wo    = (const float*)d_in[5];
    const float* bo    = (const float*)d_in[6];
    float* out = (float*)d_out;

    proj_kernel  <<<dim3(MTOT/64, DD/64, 3), 256>>>(query, key, value, Wq, bq);
    attn_kernel  <<<dim3(SS/64, BB*HH),      256>>>();
    outproj_kernel<<<dim3(MTOT/64, DD/64),   256>>>(Wo, bo, out);
}